// round 13
// baseline (speedup 1.0000x reference)
#include <cuda_runtime.h>
#include <cuda_fp16.h>
#include <cstdint>

// Problem constants (fixed by the dataset)
#define B_   2
#define S_   1024
#define D_   1024
#define VC_  8192
#define K_   4
#define V_   32000
#define BS_  (B_ * S_)   // 2048

// ---------------------------------------------------------------------------
// Device-global scratch (allocation-free rule)
// ---------------------------------------------------------------------------
__device__ __half         g_lh[BS_ * VC_];      // 32 MB f16 logits
__device__ __half         g_xh[BS_ * D_];       // 4 MB  f16 X
__device__ __half         g_wh[VC_ * D_];       // 16 MB f16 W
__device__ unsigned short g_codes[V_ * K_];     // 256 KB packed hash codes
__device__ unsigned int   g_flags[16];          // per-row-block GEMM completion
__device__ unsigned int   g_xf[16];             // X chunk converted
__device__ unsigned int   g_wf[64];             // W chunk converted
__device__ unsigned int   g_prep_ctr;           // prep items completed
__device__ unsigned int   g_ctr;                // work-queue counter

// ---------------------------------------------------------------------------
// Tiny reset kernel (graph-replay determinism)
// ---------------------------------------------------------------------------
__global__ void reset_kernel() {
    int i = threadIdx.x;
    if (i < 16) { g_flags[i] = 0; g_xf[i] = 0; }
    if (i < 64) g_wf[i] = 0;
    if (i == 64) { g_ctr = 0; g_prep_ctr = 0; }
}

// ---------------------------------------------------------------------------
// Persistent fused kernel work queue:
//   items 0..79      : prep (0..15 X chunks, 16..79 W chunks; each also 1/80 hash)
//   items 80..1103   : GEMM tiles, row-block-major (rb = (item-80)/64)
//   items 1104..1615 : gather blocks (4 rows each)
// All waits reference strictly-earlier queue items -> deadlock-free.
// ---------------------------------------------------------------------------
#define BM 128
#define BN 128
#define BK 32
#define HPAD 40   // halves per smem row -> 80B pitch
#define NS 4      // pipeline stages

#define AS_BYTES (BM * HPAD * 2)   // 10240
#define BSB_BYTES (BN * HPAD * 2)  // 10240
#define FUSED_SMEM (NS * (AS_BYTES + BSB_BYTES))   // 81920

#define TILES_PER_RB (VC_ / BN)               // 64
#define N_PREP_ITEMS 80
#define N_GEMM_ITEMS (TILES_PER_RB * (BS_ / BM))   // 1024
#define N_GATHER_ITEMS (BS_ / 4)              // 512
#define N_ITEMS (N_PREP_ITEMS + N_GEMM_ITEMS + N_GATHER_ITEMS)   // 1616
#define V_PER_PREP (V_ / N_PREP_ITEMS)        // 400

__device__ __forceinline__ uint32_t smem_u32(const void* p) {
    uint32_t a;
    asm("{ .reg .u64 t; cvta.to.shared.u64 t, %1; cvt.u32.u64 %0, t; }"
        : "=r"(a) : "l"(p));
    return a;
}
__device__ __forceinline__ void cpa16(uint32_t dst, const void* src) {
    asm volatile("cp.async.cg.shared.global [%0], [%1], 16;"
                 :: "r"(dst), "l"(src) : "memory");
}
#define CP_COMMIT() asm volatile("cp.async.commit_group;" ::: "memory")
#define CP_WAIT(n)  asm volatile("cp.async.wait_group %0;" :: "n"(n) : "memory")

__device__ __forceinline__ void ldmx4(uint32_t& r0, uint32_t& r1,
                                      uint32_t& r2, uint32_t& r3, uint32_t addr) {
    asm volatile("ldmatrix.sync.aligned.m8n8.x4.shared.b16 {%0,%1,%2,%3}, [%4];"
                 : "=r"(r0), "=r"(r1), "=r"(r2), "=r"(r3) : "r"(addr));
}
__device__ __forceinline__ unsigned ld_acquire(const unsigned* p) {
    unsigned v;
    asm volatile("ld.acquire.gpu.global.u32 %0, [%1];" : "=r"(v) : "l"(p) : "memory");
    return v;
}

// ---- prep item: convert one 128-row chunk of X or W + 1/80 of hash --------
__device__ void prep_role(int item, const float* __restrict__ X,
                          const float* __restrict__ W,
                          const int* __restrict__ p,
                          const int* __restrict__ a,
                          const int* __restrict__ b) {
    const int tid = threadIdx.x;

    // hash share: 400 consecutive v
    const int vbase = item * V_PER_PREP;
    for (int v = vbase + tid; v < vbase + V_PER_PREP; v += 256) {
#pragma unroll
        for (int k = 0; k < K_; k++) {
            unsigned int h = (unsigned int)(v * a[k] + b[k]) % (unsigned int)p[k];
            g_codes[v * K_ + k] = (unsigned short)(h & (VC_ - 1));
        }
    }

    // conversion share: 128 rows x 1024 f32 = 32768 float4
    const float4* src;
    uint2* dst;
    if (item < 16) {
        src = (const float4*)(X + (size_t)item * 128 * D_);
        dst = (uint2*)(g_xh + (size_t)item * 128 * D_);
    } else {
        int c = item - 16;
        src = (const float4*)(W + (size_t)c * 128 * D_);
        dst = (uint2*)(g_wh + (size_t)c * 128 * D_);
    }
    for (int i = tid; i < 128 * D_ / 4; i += 256) {
        float4 v = src[i];
        __half2 h0 = __floats2half2_rn(v.x, v.y);
        __half2 h1 = __floats2half2_rn(v.z, v.w);
        dst[i] = make_uint2(*(uint32_t*)&h0, *(uint32_t*)&h1);
    }
    __syncthreads();
    if (tid == 0) {
        __threadfence();
        if (item < 16) atomicExch(&g_xf[item], 1u);
        else           atomicExch(&g_wf[item - 16], 1u);
        atomicAdd(&g_prep_ctr, 1u);
    }
}

__device__ void gemm_role(int rb, int tile) {
    extern __shared__ __align__(16) char sm[];
    const int tid  = threadIdx.x;
    const int lane = tid & 31;
    const int warp = tid >> 5;
    const int wm   = (warp & 3) * 32;
    const int wn   = (warp >> 2) * 64;
    const int g    = lane >> 2;
    const int t    = lane & 3;

    // wait for this tile's input chunks (earlier queue items -> bounded spin)
    if (tid == 0) {
        while (ld_acquire(&g_xf[rb]) == 0) __nanosleep(64);
        while (ld_acquire(&g_wf[tile]) == 0) __nanosleep(64);
    }
    __syncthreads();

    const int rowBase = rb * BM;
    const int colBase = tile * BN;

    const uint32_t smb = smem_u32(sm);

    const int ra = tid >> 2;
    const int c8 = (tid & 3) * 8;

    const __half* gA0 = g_xh + (size_t)(rowBase + ra) * D_ + c8;
    const __half* gA1 = g_xh + (size_t)(rowBase + ra + 64) * D_ + c8;
    const __half* gB0 = g_wh + (size_t)(colBase + ra) * D_ + c8;
    const __half* gB1 = g_wh + (size_t)(colBase + ra + 64) * D_ + c8;
    const uint32_t st0 = (ra * HPAD + c8) * 2;
    const uint32_t st1 = ((ra + 64) * HPAD + c8) * 2;

#define ISSUE_STAGE(stg)                                                     \
    {                                                                        \
        int _slot = (stg) & (NS - 1);                                        \
        int _kt = (stg) * BK;                                                \
        uint32_t _sA = smb + _slot * AS_BYTES;                               \
        uint32_t _sB = smb + NS * AS_BYTES + _slot * BSB_BYTES;              \
        cpa16(_sA + st0, gA0 + _kt);                                         \
        cpa16(_sA + st1, gA1 + _kt);                                         \
        cpa16(_sB + st0, gB0 + _kt);                                         \
        cpa16(_sB + st1, gB1 + _kt);                                         \
        CP_COMMIT();                                                         \
    }

    const int aRow = wm + (lane & 7) + ((lane & 8) ? 8 : 0);
    const int aCol = (lane & 16) ? 8 : 0;
    const int bRow = wn + (lane & 7) + ((lane & 16) ? 8 : 0);
    const int bCol = ((lane & 8) ? 8 : 0);

    float acc[2][8][4];
#pragma unroll
    for (int mt = 0; mt < 2; mt++)
#pragma unroll
        for (int nt = 0; nt < 8; nt++)
#pragma unroll
            for (int i = 0; i < 4; i++) acc[mt][nt][i] = 0.0f;

    ISSUE_STAGE(0);
    ISSUE_STAGE(1);
    ISSUE_STAGE(2);

    const int NCHUNK = D_ / BK;   // 32
    for (int c = 0; c < NCHUNK; c++) {
        if (c < NCHUNK - 2) { CP_WAIT(2); } else { CP_WAIT(0); }
        __syncthreads();

        const int slot = c & (NS - 1);
        uint32_t asBase = smb + slot * AS_BYTES;
        uint32_t bsBase = smb + NS * AS_BYTES + slot * BSB_BYTES;

#pragma unroll
        for (int s = 0; s < 2; s++) {
            uint32_t af[2][4];
            uint32_t bf[8][2];
#pragma unroll
            for (int mt = 0; mt < 2; mt++) {
                uint32_t addr = asBase +
                    (((aRow + mt * 16) * HPAD) + (aCol + s * 16)) * 2;
                ldmx4(af[mt][0], af[mt][1], af[mt][2], af[mt][3], addr);
            }
#pragma unroll
            for (int ntp = 0; ntp < 4; ntp++) {
                uint32_t addr = bsBase +
                    (((bRow + ntp * 16) * HPAD) + (bCol + s * 16)) * 2;
                ldmx4(bf[2 * ntp][0], bf[2 * ntp][1],
                      bf[2 * ntp + 1][0], bf[2 * ntp + 1][1], addr);
            }
#pragma unroll
            for (int mt = 0; mt < 2; mt++)
#pragma unroll
                for (int nt = 0; nt < 8; nt++) {
                    asm volatile(
                        "mma.sync.aligned.m16n8k16.row.col.f32.f16.f16.f32 "
                        "{%0,%1,%2,%3},{%4,%5,%6,%7},{%8,%9},{%0,%1,%2,%3};"
                        : "+f"(acc[mt][nt][0]), "+f"(acc[mt][nt][1]),
                          "+f"(acc[mt][nt][2]), "+f"(acc[mt][nt][3])
                        : "r"(af[mt][0]), "r"(af[mt][1]),
                          "r"(af[mt][2]), "r"(af[mt][3]),
                          "r"(bf[nt][0]), "r"(bf[nt][1]));
                }
        }

        if (c + NS - 1 < NCHUNK) ISSUE_STAGE(c + NS - 1);
    }

    // epilogue: f16 logits (normal stores -> stay L2-resident for gather)
#pragma unroll
    for (int mt = 0; mt < 2; mt++) {
#pragma unroll
        for (int nt = 0; nt < 8; nt++) {
            int r = rowBase + wm + mt * 16 + g;
            int c = colBase + wn + nt * 8 + 2 * t;
            __half2 h0 = __floats2half2_rn(acc[mt][nt][0], acc[mt][nt][1]);
            __half2 h1 = __floats2half2_rn(acc[mt][nt][2], acc[mt][nt][3]);
            *(uint32_t*)(g_lh + (size_t)r * VC_ + c)       = *(uint32_t*)&h0;
            *(uint32_t*)(g_lh + (size_t)(r + 8) * VC_ + c) = *(uint32_t*)&h1;
        }
    }
    __syncthreads();
    if (tid == 0) {
        __threadfence();
        atomicAdd(&g_flags[rb], 1u);
    }
#undef ISSUE_STAGE
}

__device__ void gather_role(int gidx, float* __restrict__ out) {
    extern __shared__ __align__(16) char sm[];
    __half* sh = (__half*)sm;            // uses first 64 KB of the pool
    const int bs0 = gidx * 4;
    const int rb  = bs0 / BM;
    const int tid = threadIdx.x;

    if (tid == 0) {
        while (ld_acquire(&g_prep_ctr) < N_PREP_ITEMS) __nanosleep(128);
        while (ld_acquire(&g_flags[rb]) < TILES_PER_RB) __nanosleep(128);
    }
    __syncthreads();

    const __half* L = g_lh + (size_t)bs0 * VC_;
    for (int i = tid; i < VC_ / 2; i += 256) {
        int j0 = i * 2;
        unsigned u0 = *(const unsigned*)(L + j0);
        unsigned u1 = *(const unsigned*)(L + VC_ + j0);
        unsigned u2 = *(const unsigned*)(L + 2 * VC_ + j0);
        unsigned u3 = *(const unsigned*)(L + 3 * VC_ + j0);
        *(uint2*)(sh + j0 * 4) =
            make_uint2(__byte_perm(u0, u1, 0x5410), __byte_perm(u2, u3, 0x5410));
        *(uint2*)(sh + (j0 + 1) * 4) =
            make_uint2(__byte_perm(u0, u1, 0x7632), __byte_perm(u2, u3, 0x7632));
    }
    __syncthreads();

    float* o0 = out + (size_t)bs0 * V_;
    float* o1 = o0 + V_;
    float* o2 = o1 + V_;
    float* o3 = o2 + V_;

#pragma unroll
    for (int c = 0; c < 32; c++) {
        int v0 = c * 1024 + tid * 4;
        if (v0 < V_) {
            const uint4* cp = (const uint4*)(g_codes + (size_t)v0 * K_);
            uint4 p0 = cp[0];
            uint4 p1 = cp[1];
            unsigned cw[8] = {p0.x, p0.y, p0.z, p0.w, p1.x, p1.y, p1.z, p1.w};

            float s0[4], s1[4], s2[4], s3[4];
#pragma unroll
            for (int vi = 0; vi < 4; vi++) {
                float a0 = 0.f, a1 = 0.f, a2 = 0.f, a3 = 0.f;
#pragma unroll
                for (int h = 0; h < 2; h++) {
                    unsigned w = cw[vi * 2 + h];
                    int ja = w & 0xFFFF, jb = w >> 16;
                    uint2 qa = *(const uint2*)(sh + ja * 4);
                    float2 fa01 = __half22float2(*(const __half2*)&qa.x);
                    float2 fa23 = __half22float2(*(const __half2*)&qa.y);
                    a0 += fa01.x; a1 += fa01.y; a2 += fa23.x; a3 += fa23.y;
                    uint2 qb = *(const uint2*)(sh + jb * 4);
                    float2 fb01 = __half22float2(*(const __half2*)&qb.x);
                    float2 fb23 = __half22float2(*(const __half2*)&qb.y);
                    a0 += fb01.x; a1 += fb01.y; a2 += fb23.x; a3 += fb23.y;
                }
                s0[vi] = a0 * 0.25f; s1[vi] = a1 * 0.25f;
                s2[vi] = a2 * 0.25f; s3[vi] = a3 * 0.25f;
            }
            __stwt((float4*)(o0 + v0), make_float4(s0[0], s0[1], s0[2], s0[3]));
            __stwt((float4*)(o1 + v0), make_float4(s1[0], s1[1], s1[2], s1[3]));
            __stwt((float4*)(o2 + v0), make_float4(s2[0], s2[1], s2[2], s2[3]));
            __stwt((float4*)(o3 + v0), make_float4(s3[0], s3[1], s3[2], s3[3]));
        }
    }
}

__global__ __launch_bounds__(256, 2) void fused_kernel(
    float* __restrict__ out,
    const float* __restrict__ X, const float* __restrict__ W,
    const int* __restrict__ p, const int* __restrict__ a,
    const int* __restrict__ b) {
    __shared__ int s_item;
    for (;;) {
        __syncthreads();   // protect s_item WAR + smem reuse across items
        if (threadIdx.x == 0)
            s_item = (int)atomicAdd(&g_ctr, 1u);
        __syncthreads();
        int item = s_item;
        if (item >= N_ITEMS) return;
        if (item < N_PREP_ITEMS)
            prep_role(item, X, W, p, a, b);
        else if (item < N_PREP_ITEMS + N_GEMM_ITEMS) {
            int gi = item - N_PREP_ITEMS;
            gemm_role(gi / TILES_PER_RB, gi % TILES_PER_RB);
        } else {
            gather_role(item - N_PREP_ITEMS - N_GEMM_ITEMS, out);
        }
    }
}

// ---------------------------------------------------------------------------
// Launch
// ---------------------------------------------------------------------------
extern "C" void kernel_launch(void* const* d_in, const int* in_sizes, int n_in,
                              void* d_out, int out_size) {
    const float* x = (const float*)d_in[0];
    const float* W = (const float*)d_in[1];
    const int*   p = (const int*)d_in[2];
    const int*   a = (const int*)d_in[3];
    const int*   b = (const int*)d_in[4];
    float* out = (float*)d_out;

    reset_kernel<<<1, 96>>>();

    int nsm = 148;
    cudaDeviceGetAttribute(&nsm, cudaDevAttrMultiProcessorCount, 0);

    cudaFuncSetAttribute(fused_kernel, cudaFuncAttributeMaxDynamicSharedMemorySize,
                         FUSED_SMEM);
    fused_kernel<<<2 * nsm, 256, FUSED_SMEM>>>(out, x, W, p, a, b);
}

// round 15
// speedup vs baseline: 1.0812x; 1.0812x over previous
#include <cuda_runtime.h>
#include <cuda_fp16.h>
#include <cstdint>

// Problem constants (fixed by the dataset)
#define B_   2
#define S_   1024
#define D_   1024
#define VC_  8192
#define K_   4
#define V_   32000
#define BS_  (B_ * S_)   // 2048

// ---------------------------------------------------------------------------
// Device-global scratch (allocation-free rule)
// ---------------------------------------------------------------------------
__device__ __half         g_lh[BS_ * VC_];      // 32 MB f16 logits
__device__ __half         g_xh[BS_ * D_];       // 4 MB  f16 X
__device__ __half         g_wh[VC_ * D_];       // 16 MB f16 W
__device__ unsigned short g_codes[V_ * K_];     // 256 KB packed hash codes
__device__ unsigned int   g_flags[16];          // per-row-block completion
__device__ unsigned int   g_ctr;                // work-queue counter

// ---------------------------------------------------------------------------
// Kernel 1: fused convert (X,W -> f16, MLP=4/thread) + hash + queue reset
// ---------------------------------------------------------------------------
#define NX4 ((BS_ * D_) / 4)   // 524288 float4
#define NW4 ((VC_ * D_) / 4)   // 2097152 float4
#define NCV ((NX4 + NW4) / 4)  // 655360 convert threads, 4 float4 each
#define NPREP (NCV + V_)
__global__ __launch_bounds__(256) void prep_kernel(const float* __restrict__ X,
                                                   const float* __restrict__ W,
                                                   const int* __restrict__ p,
                                                   const int* __restrict__ a,
                                                   const int* __restrict__ b) {
    int i = blockIdx.x * blockDim.x + threadIdx.x;
    if (i < 16) g_flags[i] = 0;
    if (i == 16) g_ctr = 0;
    if (i < NCV) {
        // 4 coalesced passes; pass k covers [k*NCV, (k+1)*NCV) -> branch is
        // uniform per pass (X for k=0, W for k>=1 except boundary warp).
#pragma unroll
        for (int k = 0; k < 4; k++) {
            int idx = i + k * NCV;
            float4 v;
            uint2* dst;
            if (idx < NX4) {
                v = ((const float4*)X)[idx];
                dst = (uint2*)g_xh + idx;
            } else {
                int j = idx - NX4;
                v = ((const float4*)W)[j];
                dst = (uint2*)g_wh + j;
            }
            __half2 h0 = __floats2half2_rn(v.x, v.y);
            __half2 h1 = __floats2half2_rn(v.z, v.w);
            *dst = make_uint2(*(uint32_t*)&h0, *(uint32_t*)&h1);
        }
    } else if (i < NPREP) {
        int v = i - NCV;
#pragma unroll
        for (int k = 0; k < K_; k++) {
            unsigned int h = (unsigned int)(v * a[k] + b[k]) % (unsigned int)p[k];
            g_codes[v * K_ + k] = (unsigned short)(h & (VC_ - 1));
        }
    }
}

// ---------------------------------------------------------------------------
// Persistent fused kernel: work queue of 1536 items.
//   items 0..1023    : GEMM tiles, row-block-major (rb = item/64)
//   items 1024..1535 : gather blocks (4 rows each), same rb order
// Gather items are only handed out after ALL GEMM items are grabbed, so no
// slot spins while producer work is still queued -> deadlock-free overlap.
// ---------------------------------------------------------------------------
#define BM 128
#define BN 128
#define BK 32
#define HPAD 40   // halves per smem row -> 80B pitch
#define NS 4      // pipeline stages

#define AS_BYTES (BM * HPAD * 2)   // 10240
#define BSB_BYTES (BN * HPAD * 2)  // 10240
#define FUSED_SMEM (NS * (AS_BYTES + BSB_BYTES))   // 81920

#define TILES_PER_RB (VC_ / BN)               // 64
#define N_GEMM_ITEMS (TILES_PER_RB * (BS_ / BM))   // 1024
#define N_GATHER_ITEMS (BS_ / 4)              // 512
#define N_ITEMS (N_GEMM_ITEMS + N_GATHER_ITEMS)    // 1536

__device__ __forceinline__ uint32_t smem_u32(const void* p) {
    uint32_t a;
    asm("{ .reg .u64 t; cvta.to.shared.u64 t, %1; cvt.u32.u64 %0, t; }"
        : "=r"(a) : "l"(p));
    return a;
}
__device__ __forceinline__ void cpa16(uint32_t dst, const void* src) {
    asm volatile("cp.async.cg.shared.global [%0], [%1], 16;"
                 :: "r"(dst), "l"(src) : "memory");
}
#define CP_COMMIT() asm volatile("cp.async.commit_group;" ::: "memory")
#define CP_WAIT(n)  asm volatile("cp.async.wait_group %0;" :: "n"(n) : "memory")

__device__ __forceinline__ void ldmx4(uint32_t& r0, uint32_t& r1,
                                      uint32_t& r2, uint32_t& r3, uint32_t addr) {
    asm volatile("ldmatrix.sync.aligned.m8n8.x4.shared.b16 {%0,%1,%2,%3}, [%4];"
                 : "=r"(r0), "=r"(r1), "=r"(r2), "=r"(r3) : "r"(addr));
}
__device__ __forceinline__ unsigned ld_acquire(const unsigned* p) {
    unsigned v;
    asm volatile("ld.acquire.gpu.global.u32 %0, [%1];" : "=r"(v) : "l"(p) : "memory");
    return v;
}

__device__ void gemm_role(int rb, int tile) {
    extern __shared__ __align__(16) char sm[];
    const int tid  = threadIdx.x;
    const int lane = tid & 31;
    const int warp = tid >> 5;
    const int wm   = (warp & 3) * 32;
    const int wn   = (warp >> 2) * 64;
    const int g    = lane >> 2;
    const int t    = lane & 3;

    const int rowBase = rb * BM;
    const int colBase = tile * BN;

    const uint32_t smb = smem_u32(sm);

    const int ra = tid >> 2;
    const int c8 = (tid & 3) * 8;

    const __half* gA0 = g_xh + (size_t)(rowBase + ra) * D_ + c8;
    const __half* gA1 = g_xh + (size_t)(rowBase + ra + 64) * D_ + c8;
    const __half* gB0 = g_wh + (size_t)(colBase + ra) * D_ + c8;
    const __half* gB1 = g_wh + (size_t)(colBase + ra + 64) * D_ + c8;
    const uint32_t st0 = (ra * HPAD + c8) * 2;
    const uint32_t st1 = ((ra + 64) * HPAD + c8) * 2;

#define ISSUE_STAGE(stg)                                                     \
    {                                                                        \
        int _slot = (stg) & (NS - 1);                                        \
        int _kt = (stg) * BK;                                                \
        uint32_t _sA = smb + _slot * AS_BYTES;                               \
        uint32_t _sB = smb + NS * AS_BYTES + _slot * BSB_BYTES;              \
        cpa16(_sA + st0, gA0 + _kt);                                         \
        cpa16(_sA + st1, gA1 + _kt);                                         \
        cpa16(_sB + st0, gB0 + _kt);                                         \
        cpa16(_sB + st1, gB1 + _kt);                                         \
        CP_COMMIT();                                                         \
    }

    const int aRow = wm + (lane & 7) + ((lane & 8) ? 8 : 0);
    const int aCol = (lane & 16) ? 8 : 0;
    const int bRow = wn + (lane & 7) + ((lane & 16) ? 8 : 0);
    const int bCol = ((lane & 8) ? 8 : 0);

    float acc[2][8][4];
#pragma unroll
    for (int mt = 0; mt < 2; mt++)
#pragma unroll
        for (int nt = 0; nt < 8; nt++)
#pragma unroll
            for (int i = 0; i < 4; i++) acc[mt][nt][i] = 0.0f;

    ISSUE_STAGE(0);
    ISSUE_STAGE(1);
    ISSUE_STAGE(2);

    const int NCHUNK = D_ / BK;   // 32
    for (int c = 0; c < NCHUNK; c++) {
        if (c < NCHUNK - 2) { CP_WAIT(2); } else { CP_WAIT(0); }
        __syncthreads();

        const int slot = c & (NS - 1);
        uint32_t asBase = smb + slot * AS_BYTES;
        uint32_t bsBase = smb + NS * AS_BYTES + slot * BSB_BYTES;

#pragma unroll
        for (int s = 0; s < 2; s++) {
            uint32_t af[2][4];
            uint32_t bf[8][2];
#pragma unroll
            for (int mt = 0; mt < 2; mt++) {
                uint32_t addr = asBase +
                    (((aRow + mt * 16) * HPAD) + (aCol + s * 16)) * 2;
                ldmx4(af[mt][0], af[mt][1], af[mt][2], af[mt][3], addr);
            }
#pragma unroll
            for (int ntp = 0; ntp < 4; ntp++) {
                uint32_t addr = bsBase +
                    (((bRow + ntp * 16) * HPAD) + (bCol + s * 16)) * 2;
                ldmx4(bf[2 * ntp][0], bf[2 * ntp][1],
                      bf[2 * ntp + 1][0], bf[2 * ntp + 1][1], addr);
            }
#pragma unroll
            for (int mt = 0; mt < 2; mt++)
#pragma unroll
                for (int nt = 0; nt < 8; nt++) {
                    asm volatile(
                        "mma.sync.aligned.m16n8k16.row.col.f32.f16.f16.f32 "
                        "{%0,%1,%2,%3},{%4,%5,%6,%7},{%8,%9},{%0,%1,%2,%3};"
                        : "+f"(acc[mt][nt][0]), "+f"(acc[mt][nt][1]),
                          "+f"(acc[mt][nt][2]), "+f"(acc[mt][nt][3])
                        : "r"(af[mt][0]), "r"(af[mt][1]),
                          "r"(af[mt][2]), "r"(af[mt][3]),
                          "r"(bf[nt][0]), "r"(bf[nt][1]));
                }
        }

        if (c + NS - 1 < NCHUNK) ISSUE_STAGE(c + NS - 1);
    }

    // epilogue: f16 logits (normal stores -> stay L2-resident for gather)
#pragma unroll
    for (int mt = 0; mt < 2; mt++) {
#pragma unroll
        for (int nt = 0; nt < 8; nt++) {
            int r = rowBase + wm + mt * 16 + g;
            int c = colBase + wn + nt * 8 + 2 * t;
            __half2 h0 = __floats2half2_rn(acc[mt][nt][0], acc[mt][nt][1]);
            __half2 h1 = __floats2half2_rn(acc[mt][nt][2], acc[mt][nt][3]);
            *(uint32_t*)(g_lh + (size_t)r * VC_ + c)       = *(uint32_t*)&h0;
            *(uint32_t*)(g_lh + (size_t)(r + 8) * VC_ + c) = *(uint32_t*)&h1;
        }
    }
    __syncthreads();
    if (tid == 0) {
        __threadfence();
        atomicAdd(&g_flags[rb], 1u);
    }
#undef ISSUE_STAGE
}

__device__ void gather_role(int gidx, float* __restrict__ out) {
    extern __shared__ __align__(16) char sm[];
    __half* sh = (__half*)sm;            // uses first 64 KB of the pool
    const int bs0 = gidx * 4;
    const int rb  = bs0 / BM;
    const int tid = threadIdx.x;

    if (tid == 0) {
        while (ld_acquire(&g_flags[rb]) < TILES_PER_RB) __nanosleep(128);
    }
    __syncthreads();

    const __half* L = g_lh + (size_t)bs0 * VC_;
    for (int i = tid; i < VC_ / 2; i += 256) {
        int j0 = i * 2;
        unsigned u0 = *(const unsigned*)(L + j0);
        unsigned u1 = *(const unsigned*)(L + VC_ + j0);
        unsigned u2 = *(const unsigned*)(L + 2 * VC_ + j0);
        unsigned u3 = *(const unsigned*)(L + 3 * VC_ + j0);
        *(uint2*)(sh + j0 * 4) =
            make_uint2(__byte_perm(u0, u1, 0x5410), __byte_perm(u2, u3, 0x5410));
        *(uint2*)(sh + (j0 + 1) * 4) =
            make_uint2(__byte_perm(u0, u1, 0x7632), __byte_perm(u2, u3, 0x7632));
    }
    __syncthreads();

    float* o0 = out + (size_t)bs0 * V_;
    float* o1 = o0 + V_;
    float* o2 = o1 + V_;
    float* o3 = o2 + V_;

#pragma unroll
    for (int c = 0; c < 32; c++) {
        int v0 = c * 1024 + tid * 4;
        if (v0 < V_) {
            const uint4* cp = (const uint4*)(g_codes + (size_t)v0 * K_);
            uint4 p0 = cp[0];
            uint4 p1 = cp[1];
            unsigned cw[8] = {p0.x, p0.y, p0.z, p0.w, p1.x, p1.y, p1.z, p1.w};

            float s0[4], s1[4], s2[4], s3[4];
#pragma unroll
            for (int vi = 0; vi < 4; vi++) {
                float a0 = 0.f, a1 = 0.f, a2 = 0.f, a3 = 0.f;
#pragma unroll
                for (int h = 0; h < 2; h++) {
                    unsigned w = cw[vi * 2 + h];
                    int ja = w & 0xFFFF, jb = w >> 16;
                    uint2 qa = *(const uint2*)(sh + ja * 4);
                    float2 fa01 = __half22float2(*(const __half2*)&qa.x);
                    float2 fa23 = __half22float2(*(const __half2*)&qa.y);
                    a0 += fa01.x; a1 += fa01.y; a2 += fa23.x; a3 += fa23.y;
                    uint2 qb = *(const uint2*)(sh + jb * 4);
                    float2 fb01 = __half22float2(*(const __half2*)&qb.x);
                    float2 fb23 = __half22float2(*(const __half2*)&qb.y);
                    a0 += fb01.x; a1 += fb01.y; a2 += fb23.x; a3 += fb23.y;
                }
                s0[vi] = a0 * 0.25f; s1[vi] = a1 * 0.25f;
                s2[vi] = a2 * 0.25f; s3[vi] = a3 * 0.25f;
            }
            __stwt((float4*)(o0 + v0), make_float4(s0[0], s0[1], s0[2], s0[3]));
            __stwt((float4*)(o1 + v0), make_float4(s1[0], s1[1], s1[2], s1[3]));
            __stwt((float4*)(o2 + v0), make_float4(s2[0], s2[1], s2[2], s2[3]));
            __stwt((float4*)(o3 + v0), make_float4(s3[0], s3[1], s3[2], s3[3]));
        }
    }
}

__global__ __launch_bounds__(256, 2) void fused_kernel(float* __restrict__ out) {
    __shared__ int s_item;
    for (;;) {
        __syncthreads();   // protect s_item WAR + smem reuse across items
        if (threadIdx.x == 0)
            s_item = (int)atomicAdd(&g_ctr, 1u);
        __syncthreads();
        int item = s_item;
        if (item >= N_ITEMS) return;
        if (item < N_GEMM_ITEMS)
            gemm_role(item / TILES_PER_RB, item % TILES_PER_RB);
        else
            gather_role(item - N_GEMM_ITEMS, out);
    }
}

// ---------------------------------------------------------------------------
// Launch
// ---------------------------------------------------------------------------
extern "C" void kernel_launch(void* const* d_in, const int* in_sizes, int n_in,
                              void* d_out, int out_size) {
    const float* x = (const float*)d_in[0];
    const float* W = (const float*)d_in[1];
    const int*   p = (const int*)d_in[2];
    const int*   a = (const int*)d_in[3];
    const int*   b = (const int*)d_in[4];
    float* out = (float*)d_out;

    prep_kernel<<<(NPREP + 255) / 256, 256>>>(x, W, p, a, b);

    int nsm = 148;
    cudaDeviceGetAttribute(&nsm, cudaDevAttrMultiProcessorCount, 0);

    cudaFuncSetAttribute(fused_kernel, cudaFuncAttributeMaxDynamicSharedMemorySize,
                         FUSED_SMEM);
    fused_kernel<<<2 * nsm, 256, FUSED_SMEM>>>(out);
}